// round 1
// baseline (speedup 1.0000x reference)
#include <cuda_runtime.h>
#include <math.h>

#define BSZ 4
#define LSEQ 4096
#define DD 1024
#define CH 64
#define NCH (LSEQ / CH)   // 64
#define MROWS (BSZ * LSEQ) // 16384

// Scratch (device globals; no allocations allowed)
__device__ float2 g_u[(size_t)BSZ * LSEQ * DD];        // u, then in-place local-scanned x (128 MiB)
__device__ float  g_xr[(size_t)BSZ * LSEQ * 2 * DD];   // [re | im] concat, GEMM2 input (128 MiB)
__device__ float2 g_last[BSZ * NCH * DD];              // per-chunk last local state
__device__ float2 g_cin[BSZ * NCH * DD];               // per-chunk carry-in (full state)

// ---------------------------------------------------------------------------
// GEMM: C[M,N] = A[M,K] @ W[N,K]^T + bias[N]   (optionally ReLU)
// 128x128 block tile, BK=8, 256 threads, 8x8 per thread
// ---------------------------------------------------------------------------
template <bool RELU>
__global__ __launch_bounds__(256) void gemm_nt(
    const float* __restrict__ A,
    const float* __restrict__ W,
    const float* __restrict__ bias,
    float* __restrict__ C,
    int M, int N, int K)
{
    const int BM = 128, BN = 128, BK = 8, TM = 8, TN = 8;
    __shared__ float As[BK][BM];
    __shared__ float Bs[BK][BN];

    int tid = threadIdx.x;
    int tx = tid % (BN / TN);   // 0..15 (n dir)
    int ty = tid / (BN / TN);   // 0..15 (m dir)
    int m0 = blockIdx.y * BM;
    int n0 = blockIdx.x * BN;

    // loader mapping: each thread loads one float4 of A and one of W per k-tile
    int lrow = tid >> 1;          // 0..127
    int lk4  = (tid & 1) * 4;     // 0 or 4

    const float* Aptr = A + (size_t)(m0 + lrow) * K + lk4;
    const float* Wptr = W + (size_t)(n0 + lrow) * K + lk4;

    float acc[TM][TN];
#pragma unroll
    for (int i = 0; i < TM; i++)
#pragma unroll
        for (int j = 0; j < TN; j++) acc[i][j] = 0.0f;

    for (int k0 = 0; k0 < K; k0 += BK) {
        float4 av = *(const float4*)(Aptr + k0);
        float4 wv = *(const float4*)(Wptr + k0);
        As[lk4 + 0][lrow] = av.x;
        As[lk4 + 1][lrow] = av.y;
        As[lk4 + 2][lrow] = av.z;
        As[lk4 + 3][lrow] = av.w;
        Bs[lk4 + 0][lrow] = wv.x;
        Bs[lk4 + 1][lrow] = wv.y;
        Bs[lk4 + 2][lrow] = wv.z;
        Bs[lk4 + 3][lrow] = wv.w;
        __syncthreads();

#pragma unroll
        for (int kk = 0; kk < BK; kk++) {
            float a[TM], b[TN];
            *(float4*)(a)     = *(const float4*)&As[kk][ty * TM];
            *(float4*)(a + 4) = *(const float4*)&As[kk][ty * TM + 4];
            *(float4*)(b)     = *(const float4*)&Bs[kk][tx * TN];
            *(float4*)(b + 4) = *(const float4*)&Bs[kk][tx * TN + 4];
#pragma unroll
            for (int i = 0; i < TM; i++)
#pragma unroll
                for (int j = 0; j < TN; j++)
                    acc[i][j] = fmaf(a[i], b[j], acc[i][j]);
        }
        __syncthreads();
    }

    // epilogue
    float bsv[TN];
#pragma unroll
    for (int j = 0; j < TN; j++) bsv[j] = bias[n0 + tx * TN + j];

#pragma unroll
    for (int i = 0; i < TM; i++) {
        size_t row = (size_t)(m0 + ty * TM + i);
        float out[TN];
#pragma unroll
        for (int j = 0; j < TN; j++) {
            float v = acc[i][j] + bsv[j];
            out[j] = RELU ? fmaxf(v, 0.0f) : v;
        }
        float* cp = C + row * N + n0 + tx * TN;
        *(float4*)(cp)     = *(const float4*)(out);
        *(float4*)(cp + 4) = *(const float4*)(out + 4);
    }
}

// ---------------------------------------------------------------------------
// Scan phase 1: local sequential scan within each chunk (state starts at 0),
// in-place on g_u; record last state per chunk.
// ---------------------------------------------------------------------------
__global__ __launch_bounds__(256) void scan_local(const float* __restrict__ plog)
{
    int t = blockIdx.x * blockDim.x + threadIdx.x;  // B*NCH*D threads
    int d = t % DD;
    int c = (t / DD) % NCH;
    int b = t / (DD * NCH);

    float v  = expf(plog[d]);
    float th = expf(plog[DD + d]);
    float r  = expf(-v);
    float sn, cs;
    sincosf(th, &sn, &cs);
    float lre = r * cs, lim = r * sn;

    size_t base = ((size_t)(b * LSEQ + c * CH)) * DD + d;
    float2 s = make_float2(0.0f, 0.0f);
    float2 unext = g_u[base];
#pragma unroll 4
    for (int j = 0; j < CH; j++) {
        float2 u = unext;
        if (j + 1 < CH) unext = g_u[base + (size_t)(j + 1) * DD];
        float sre = fmaf(lre, s.x, fmaf(-lim, s.y, u.x));
        float sim = fmaf(lre, s.y, fmaf( lim, s.x, u.y));
        s = make_float2(sre, sim);
        g_u[base + (size_t)j * DD] = s;
    }
    g_last[(b * NCH + c) * DD + d] = s;
}

// ---------------------------------------------------------------------------
// Scan phase 2: carry scan across chunks. Lambda^CH via closed form.
// ---------------------------------------------------------------------------
__global__ __launch_bounds__(256) void scan_carry(const float* __restrict__ plog)
{
    int t = blockIdx.x * blockDim.x + threadIdx.x;  // B*D threads
    int d = t % DD;
    int b = t / DD;

    float v  = expf(plog[d]);
    float th = expf(plog[DD + d]);
    float Lr = expf(-(float)CH * v);
    float sn, cs;
    sincosf((float)CH * th, &sn, &cs);
    float Lre = Lr * cs, Lim = Lr * sn;

    float2 s = make_float2(0.0f, 0.0f);
    for (int k = 0; k < NCH; k++) {
        g_cin[(b * NCH + k) * DD + d] = s;
        float2 last = g_last[(b * NCH + k) * DD + d];
        float sre = fmaf(Lre, s.x, fmaf(-Lim, s.y, last.x));
        float sim = fmaf(Lre, s.y, fmaf( Lim, s.x, last.y));
        s = make_float2(sre, sim);
    }
}

// ---------------------------------------------------------------------------
// Scan phase 3: fixup x_t = local_t + lambda^{j+1} * carry, scale by gamma,
// write xr = [re | im] layout for GEMM2.
// ---------------------------------------------------------------------------
__global__ __launch_bounds__(256) void scan_fix(const float* __restrict__ plog)
{
    int t = blockIdx.x * blockDim.x + threadIdx.x;  // B*NCH*D threads
    int d = t % DD;
    int c = (t / DD) % NCH;
    int b = t / (DD * NCH);

    float v  = expf(plog[d]);
    float th = expf(plog[DD + d]);
    float g  = expf(plog[2 * DD + d]);
    float r  = expf(-v);
    float sn, cs;
    sincosf(th, &sn, &cs);
    float lre = r * cs, lim = r * sn;

    float2 cin = g_cin[(b * NCH + c) * DD + d];
    float pre = lre, pim = lim;  // lambda^1

    size_t base = ((size_t)(b * LSEQ + c * CH)) * DD + d;
    size_t rbase = ((size_t)(b * LSEQ + c * CH)) * (2 * DD);

#pragma unroll 4
    for (int j = 0; j < CH; j++) {
        float2 x = g_u[base + (size_t)j * DD];
        float xre = x.x + pre * cin.x - pim * cin.y;
        float xim = x.y + pre * cin.y + pim * cin.x;
        g_xr[rbase + (size_t)j * (2 * DD) + d]      = g * xre;
        g_xr[rbase + (size_t)j * (2 * DD) + DD + d] = g * xim;
        float npre = pre * lre - pim * lim;
        pim = pre * lim + pim * lre;
        pre = npre;
    }
}

// ---------------------------------------------------------------------------
extern "C" void kernel_launch(void* const* d_in, const int* in_sizes, int n_in,
                              void* d_out, int out_size)
{
    const float* inputs = (const float*)d_in[0];
    const float* Wi     = (const float*)d_in[1];
    const float* bi     = (const float*)d_in[2];
    const float* Wo     = (const float*)d_in[3];
    const float* bo     = (const float*)d_in[4];
    const float* plog   = (const float*)d_in[5];

    void* up;  cudaGetSymbolAddress(&up, g_u);
    void* xrp; cudaGetSymbolAddress(&xrp, g_xr);

    dim3 blk(256);

    // GEMM1: u = inputs @ Wi^T + bi   -> g_u (interleaved complex pairs)
    gemm_nt<false><<<dim3((2 * DD) / 128, MROWS / 128), blk>>>(
        inputs, Wi, bi, (float*)up, MROWS, 2 * DD, DD);

    // Scan
    scan_local<<<(BSZ * NCH * DD) / 256, 256>>>(plog);
    scan_carry<<<(BSZ * DD) / 256, 256>>>(plog);
    scan_fix<<<(BSZ * NCH * DD) / 256, 256>>>(plog);

    // GEMM2: out = relu(xr @ Wo^T + bo)
    gemm_nt<true><<<dim3(DD / 128, MROWS / 128), blk>>>(
        (const float*)xrp, Wo, bo, (float*)d_out, MROWS, DD, 2 * DD);
}

// round 3
// speedup vs baseline: 2.8129x; 2.8129x over previous
#include <cuda_runtime.h>
#include <cuda_bf16.h>
#include <math.h>
#include <cstdint>

#define BSZ 4
#define LSEQ 4096
#define DD 1024
#define CH 64
#define NCH (LSEQ / CH)
#define MROWS (BSZ * LSEQ)

// Scratch (device globals; no allocations allowed)
__device__ float2 g_u[(size_t)BSZ * LSEQ * DD];        // GEMM1 out (interleaved complex), then local-scanned
__device__ float  g_xr[(size_t)BSZ * LSEQ * 2 * DD];   // [re | im] concat, GEMM2 input
__device__ float2 g_last[BSZ * NCH * DD];
__device__ float2 g_cin[BSZ * NCH * DD];

// ---------------------------------------------------------------------------
// helpers
// ---------------------------------------------------------------------------
__device__ __forceinline__ uint32_t smem_to_u32(const void* p) {
    uint32_t a;
    asm("{ .reg .u64 t; cvta.to.shared.u64 t, %1; cvt.u32.u64 %0, t; }" : "=r"(a) : "l"(p));
    return a;
}
#define SWZ128(o) ((o) ^ (((o) >> 3) & 0x70))

__device__ __forceinline__ void ldsm4(uint32_t* r, uint32_t a) {
    asm volatile("ldmatrix.sync.aligned.m8n8.x4.shared.b16 {%0,%1,%2,%3}, [%4];"
                 : "=r"(r[0]), "=r"(r[1]), "=r"(r[2]), "=r"(r[3]) : "r"(a));
}
__device__ __forceinline__ void ldsm2(uint32_t* r, uint32_t a) {
    asm volatile("ldmatrix.sync.aligned.m8n8.x2.shared.b16 {%0,%1}, [%2];"
                 : "=r"(r[0]), "=r"(r[1]) : "r"(a));
}
__device__ __forceinline__ void mma16816(float* c, const uint32_t* a, const uint32_t* b) {
    asm volatile(
        "mma.sync.aligned.m16n8k16.row.col.f32.bf16.bf16.f32 "
        "{%0,%1,%2,%3}, {%4,%5,%6,%7}, {%8,%9}, {%0,%1,%2,%3};"
        : "+f"(c[0]), "+f"(c[1]), "+f"(c[2]), "+f"(c[3])
        : "r"(a[0]), "r"(a[1]), "r"(a[2]), "r"(a[3]), "r"(b[0]), "r"(b[1]));
}

__device__ __forceinline__ uint32_t pack_hi(float a, float b, float& ra, float& rb) {
    __nv_bfloat162 h = __floats2bfloat162_rn(a, b);
    float2 bk = __bfloat1622float2(h);
    ra = a - bk.x; rb = b - bk.y;
    return *reinterpret_cast<uint32_t*>(&h);
}
__device__ __forceinline__ uint32_t pack_lo(float a, float b) {
    __nv_bfloat162 h = __floats2bfloat162_rn(a, b);
    return *reinterpret_cast<uint32_t*>(&h);
}

// ---------------------------------------------------------------------------
// Split-bf16 HMMA GEMM: C[M,N] = A[M,K] @ W[N,K]^T + bias (opt ReLU)
// CTA 128x128, BK=32 fp32, 256 thr / 8 warps, warp tile 64x32.
// SMEM stage (32KB): A tile rows r: [hi 64B | lo 64B] (32 bf16 each), B same.
// ---------------------------------------------------------------------------
static constexpr int STAGE_B = 32768;
static constexpr int SMEM_BYTES = 2 * STAGE_B;   // 64 KB

template <bool RELU>
__global__ __launch_bounds__(256, 1) void gemm_mma(
    const float* __restrict__ A,
    const float* __restrict__ W,
    const float* __restrict__ bias,
    float* __restrict__ C,
    int N, int K)
{
    extern __shared__ __align__(1024) char smem[];
    const uint32_t sbase = smem_to_u32(smem);
    const int tid = threadIdx.x;
    const int lane = tid & 31, w = tid >> 5;
    const int m0 = blockIdx.y * 128, n0 = blockIdx.x * 128;
    const int mw = (w & 1) * 64;    // warp M offset in tile
    const int nw = (w >> 1) * 32;   // warp N offset in tile

    // loader mapping: row = tid>>3 (+32i), fp32 col = (tid&7)*4
    const int lr  = tid >> 3;
    const int lcf = (tid & 7) * 4;
    const float* Ap = A + (size_t)(m0 + lr) * K + lcf;
    const float* Wp = W + (size_t)(n0 + lr) * K + lcf;

    float acc[4][4][4];
#pragma unroll
    for (int i = 0; i < 4; i++)
#pragma unroll
        for (int j = 0; j < 4; j++)
#pragma unroll
            for (int r = 0; r < 4; r++) acc[i][j][r] = 0.0f;

    float4 ra[4], rb[4];

    auto ldg = [&](int kt) {
#pragma unroll
        for (int i = 0; i < 4; i++) {
            ra[i] = *(const float4*)(Ap + (size_t)(i * 32) * K + kt * 32);
            rb[i] = *(const float4*)(Wp + (size_t)(i * 32) * K + kt * 32);
        }
    };

    auto sts = [&](int s) {
        char* stA = smem + s * STAGE_B;
        char* stB = stA + 16384;
#pragma unroll
        for (int i = 0; i < 4; i++) {
            const int r = lr + 32 * i;
            const uint32_t ho = SWZ128((uint32_t)(r * 128 + lcf * 2));
            const uint32_t lo = SWZ128((uint32_t)(r * 128 + 64 + lcf * 2));
            float e0, e1, e2, e3;
            uint2 h, l;
            h.x = pack_hi(ra[i].x, ra[i].y, e0, e1);
            h.y = pack_hi(ra[i].z, ra[i].w, e2, e3);
            l.x = pack_lo(e0, e1); l.y = pack_lo(e2, e3);
            *(uint2*)(stA + ho) = h;
            *(uint2*)(stA + lo) = l;
            h.x = pack_hi(rb[i].x, rb[i].y, e0, e1);
            h.y = pack_hi(rb[i].z, rb[i].w, e2, e3);
            l.x = pack_lo(e0, e1); l.y = pack_lo(e2, e3);
            *(uint2*)(stB + ho) = h;
            *(uint2*)(stB + lo) = l;
        }
    };

    auto compute = [&](int s) {
        const uint32_t aA = sbase + s * STAGE_B;
        const uint32_t aB = aA + 16384;
#pragma unroll
        for (int ks = 0; ks < 2; ks++) {
            uint32_t ah[4][4], al[4][4], bh[4][2], bl[4][2];
#pragma unroll
            for (int i = 0; i < 4; i++) {
                const int r = mw + i * 16 + (lane & 15);
                const uint32_t off = (uint32_t)(ks * 32 + ((lane >> 4) << 4));
                ldsm4(ah[i], aA + SWZ128((uint32_t)(r * 128) + off));
                ldsm4(al[i], aA + SWZ128((uint32_t)(r * 128) + off + 64));
            }
#pragma unroll
            for (int j = 0; j < 4; j++) {
                const int r = nw + j * 8 + (lane & 7);
                const uint32_t off = (uint32_t)(ks * 32 + ((lane >> 3) & 1) * 16);
                ldsm2(bh[j], aB + SWZ128((uint32_t)(r * 128) + off));
                ldsm2(bl[j], aB + SWZ128((uint32_t)(r * 128) + off + 64));
            }
#pragma unroll
            for (int i = 0; i < 4; i++)
#pragma unroll
                for (int j = 0; j < 4; j++) {
                    mma16816(acc[i][j], ah[i], bh[j]);
                    mma16816(acc[i][j], ah[i], bl[j]);
                    mma16816(acc[i][j], al[i], bh[j]);
                }
        }
    };

    const int NT = K / 32;
    ldg(0);
    sts(0);
    __syncthreads();

#pragma unroll 1
    for (int kt = 0; kt < NT; kt++) {
        const int s = kt & 1;
        if (kt + 1 < NT) ldg(kt + 1);
        compute(s);
        __syncthreads();
        if (kt + 1 < NT) {
            sts(s ^ 1);
            __syncthreads();
        }
    }

    // epilogue
#pragma unroll
    for (int i = 0; i < 4; i++) {
        const int mrow = m0 + mw + i * 16 + (lane >> 2);
#pragma unroll
        for (int j = 0; j < 4; j++) {
            const int ncol = n0 + nw + j * 8 + (lane & 3) * 2;
            const float b0 = bias[ncol], b1 = bias[ncol + 1];
            float2 v0 = make_float2(acc[i][j][0] + b0, acc[i][j][1] + b1);
            float2 v1 = make_float2(acc[i][j][2] + b0, acc[i][j][3] + b1);
            if (RELU) {
                v0.x = fmaxf(v0.x, 0.f); v0.y = fmaxf(v0.y, 0.f);
                v1.x = fmaxf(v1.x, 0.f); v1.y = fmaxf(v1.y, 0.f);
            }
            *(float2*)(C + (size_t)mrow * N + ncol) = v0;
            *(float2*)(C + (size_t)(mrow + 8) * N + ncol) = v1;
        }
    }
}

// ---------------------------------------------------------------------------
// Scan phase 1: local sequential scan within each chunk
// ---------------------------------------------------------------------------
__global__ __launch_bounds__(256) void scan_local(const float* __restrict__ plog)
{
    int t = blockIdx.x * blockDim.x + threadIdx.x;
    int d = t % DD;
    int c = (t / DD) % NCH;
    int b = t / (DD * NCH);

    float v  = expf(plog[d]);
    float th = expf(plog[DD + d]);
    float r  = expf(-v);
    float sn, cs;
    sincosf(th, &sn, &cs);
    float lre = r * cs, lim = r * sn;

    size_t base = ((size_t)(b * LSEQ + c * CH)) * DD + d;
    float2 s = make_float2(0.0f, 0.0f);
    float2 unext = g_u[base];
#pragma unroll 4
    for (int j = 0; j < CH; j++) {
        float2 u = unext;
        if (j + 1 < CH) unext = g_u[base + (size_t)(j + 1) * DD];
        float sre = fmaf(lre, s.x, fmaf(-lim, s.y, u.x));
        float sim = fmaf(lre, s.y, fmaf( lim, s.x, u.y));
        s = make_float2(sre, sim);
        g_u[base + (size_t)j * DD] = s;
    }
    g_last[(b * NCH + c) * DD + d] = s;
}

// ---------------------------------------------------------------------------
// Scan phase 2: carry scan across chunks
// ---------------------------------------------------------------------------
__global__ __launch_bounds__(256) void scan_carry(const float* __restrict__ plog)
{
    int t = blockIdx.x * blockDim.x + threadIdx.x;
    int d = t % DD;
    int b = t / DD;

    float v  = expf(plog[d]);
    float th = expf(plog[DD + d]);
    float Lr = expf(-(float)CH * v);
    float sn, cs;
    sincosf((float)CH * th, &sn, &cs);
    float Lre = Lr * cs, Lim = Lr * sn;

    float2 s = make_float2(0.0f, 0.0f);
    for (int k = 0; k < NCH; k++) {
        g_cin[(b * NCH + k) * DD + d] = s;
        float2 last = g_last[(b * NCH + k) * DD + d];
        float sre = fmaf(Lre, s.x, fmaf(-Lim, s.y, last.x));
        float sim = fmaf(Lre, s.y, fmaf( Lim, s.x, last.y));
        s = make_float2(sre, sim);
    }
}

// ---------------------------------------------------------------------------
// Scan phase 3: fixup + gamma + [re|im] layout
// ---------------------------------------------------------------------------
__global__ __launch_bounds__(256) void scan_fix(const float* __restrict__ plog)
{
    int t = blockIdx.x * blockDim.x + threadIdx.x;
    int d = t % DD;
    int c = (t / DD) % NCH;
    int b = t / (DD * NCH);

    float v  = expf(plog[d]);
    float th = expf(plog[DD + d]);
    float g  = expf(plog[2 * DD + d]);
    float r  = expf(-v);
    float sn, cs;
    sincosf(th, &sn, &cs);
    float lre = r * cs, lim = r * sn;

    float2 cin = g_cin[(b * NCH + c) * DD + d];
    float pre = lre, pim = lim;

    size_t base = ((size_t)(b * LSEQ + c * CH)) * DD + d;
    size_t rbase = ((size_t)(b * LSEQ + c * CH)) * (2 * DD);

#pragma unroll 4
    for (int j = 0; j < CH; j++) {
        float2 x = g_u[base + (size_t)j * DD];
        float xre = x.x + pre * cin.x - pim * cin.y;
        float xim = x.y + pre * cin.y + pim * cin.x;
        g_xr[rbase + (size_t)j * (2 * DD) + d]      = g * xre;
        g_xr[rbase + (size_t)j * (2 * DD) + DD + d] = g * xim;
        float npre = pre * lre - pim * lim;
        pim = pre * lim + pim * lre;
        pre = npre;
    }
}

// ---------------------------------------------------------------------------
extern "C" void kernel_launch(void* const* d_in, const int* in_sizes, int n_in,
                              void* d_out, int out_size)
{
    const float* inputs = (const float*)d_in[0];
    const float* Wi     = (const float*)d_in[1];
    const float* bi     = (const float*)d_in[2];
    const float* Wo     = (const float*)d_in[3];
    const float* bo     = (const float*)d_in[4];
    const float* plog   = (const float*)d_in[5];

    void* up;  cudaGetSymbolAddress(&up, g_u);
    void* xrp; cudaGetSymbolAddress(&xrp, g_xr);

    cudaFuncSetAttribute(gemm_mma<false>, cudaFuncAttributeMaxDynamicSharedMemorySize, SMEM_BYTES);
    cudaFuncSetAttribute(gemm_mma<true>,  cudaFuncAttributeMaxDynamicSharedMemorySize, SMEM_BYTES);

    // GEMM1: u = inputs @ Wi^T + bi  -> g_u
    gemm_mma<false><<<dim3((2 * DD) / 128, MROWS / 128), 256, SMEM_BYTES>>>(
        inputs, Wi, bi, (float*)up, 2 * DD, DD);

    // Scan
    scan_local<<<(BSZ * NCH * DD) / 256, 256>>>(plog);
    scan_carry<<<(BSZ * DD) / 256, 256>>>(plog);
    scan_fix<<<(BSZ * NCH * DD) / 256, 256>>>(plog);

    // GEMM2: out = relu(xr @ Wo^T + bo)
    gemm_mma<true><<<dim3(DD / 128, MROWS / 128), 256, SMEM_BYTES>>>(
        (const float*)xrp, Wo, bo, (float*)d_out, DD, 2 * DD);
}